// round 1
// baseline (speedup 1.0000x reference)
#include <cuda_runtime.h>
#include <cuda_bf16.h>

#define B_  16
#define C_  80
#define D_  1024
#define HW_ 196

// scratch: scores -> (in-place softmax) -> coef
__device__ float g_scores[B_ * C_ * HW_];

__device__ __forceinline__ float tanh_approx(float x) {
    float y;
    asm("tanh.approx.f32 %0, %1;" : "=f"(y) : "f"(x));
    return y;
}

// -----------------------------------------------------------------------------
// Kernel A: scores[b][c][hw] = sum_d tanh(img[b][d][hw] * word[c][d]) * fw[d] + fb
// grid (7 hw-tiles, 5 c-tiles, 16 b), block (32, 4).
// Each thread: hw = tx, classes c0 + ty + {0,4,8,12}. d chunked by 32 via SMEM.
// -----------------------------------------------------------------------------
__global__ __launch_bounds__(128) void scores_kernel(
    const float* __restrict__ img,   // [B, D, HW]
    const float* __restrict__ word,  // [C, D]
    const float* __restrict__ fw,    // [D]
    const float* __restrict__ fbp)   // scalar
{
    __shared__ float img_s[32][32];   // [dd][hw]
    __shared__ float word_s[16][32];  // [cc][dd]
    __shared__ float fw_s[32];

    const int tx  = threadIdx.x;           // 0..31 (hw lane)
    const int ty  = threadIdx.y;           // 0..3  (class group)
    const int tid = ty * 32 + tx;
    const int hw0 = blockIdx.x * 32;
    const int c0  = blockIdx.y * 16;
    const int b   = blockIdx.z;

    const float* imgb = img + (size_t)b * D_ * HW_;

    float acc0 = 0.f, acc1 = 0.f, acc2 = 0.f, acc3 = 0.f;

    for (int d0 = 0; d0 < D_; d0 += 32) {
        // img chunk [32 d][32 hw] (zero-pad hw >= 196)
        #pragma unroll
        for (int i = tid; i < 1024; i += 128) {
            int dd = i >> 5, l = i & 31;
            int hw = hw0 + l;
            img_s[dd][l] = (hw < HW_) ? imgb[(size_t)(d0 + dd) * HW_ + hw] : 0.f;
        }
        // word chunk [16 c][32 d]
        #pragma unroll
        for (int i = tid; i < 512; i += 128) {
            int cc = i >> 5, dd = i & 31;
            word_s[cc][dd] = word[(size_t)(c0 + cc) * D_ + d0 + dd];
        }
        if (tid < 32) fw_s[tid] = fw[d0 + tid];
        __syncthreads();

        #pragma unroll 8
        for (int dd = 0; dd < 32; dd++) {
            float iv = img_s[dd][tx];
            float w  = fw_s[dd];
            acc0 += tanh_approx(iv * word_s[ty     ][dd]) * w;
            acc1 += tanh_approx(iv * word_s[ty +  4][dd]) * w;
            acc2 += tanh_approx(iv * word_s[ty +  8][dd]) * w;
            acc3 += tanh_approx(iv * word_s[ty + 12][dd]) * w;
        }
        __syncthreads();
    }

    const int hw = hw0 + tx;
    if (hw < HW_) {
        const float fb = *fbp;
        g_scores[((size_t)b * C_ + (c0 + ty     )) * HW_ + hw] = acc0 + fb;
        g_scores[((size_t)b * C_ + (c0 + ty +  4)) * HW_ + hw] = acc1 + fb;
        g_scores[((size_t)b * C_ + (c0 + ty +  8)) * HW_ + hw] = acc2 + fb;
        g_scores[((size_t)b * C_ + (c0 + ty + 12)) * HW_ + hw] = acc3 + fb;
    }
}

// -----------------------------------------------------------------------------
// Kernel B: in-place softmax over the 196 hw positions of each (b,c) row.
// One warp per row; 1280 rows.
// -----------------------------------------------------------------------------
__global__ __launch_bounds__(256) void softmax_kernel()
{
    const int wid  = (blockIdx.x * blockDim.x + threadIdx.x) >> 5;
    const int lane = threadIdx.x & 31;
    if (wid >= B_ * C_) return;

    float* row = g_scores + (size_t)wid * HW_;

    float v[7];
    float m = -1e30f;
    #pragma unroll
    for (int k = 0; k < 7; k++) {
        int i = lane + 32 * k;
        v[k] = (i < HW_) ? row[i] : -1e30f;
        m = fmaxf(m, v[k]);
    }
    #pragma unroll
    for (int o = 16; o; o >>= 1) m = fmaxf(m, __shfl_xor_sync(0xffffffffu, m, o));

    float s = 0.f;
    #pragma unroll
    for (int k = 0; k < 7; k++) { v[k] = __expf(v[k] - m); s += v[k]; }
    #pragma unroll
    for (int o = 16; o; o >>= 1) s += __shfl_xor_sync(0xffffffffu, s, o);

    const float inv = 1.f / s;
    #pragma unroll
    for (int k = 0; k < 7; k++) {
        int i = lane + 32 * k;
        if (i < HW_) row[i] = v[k] * inv;
    }
}

// -----------------------------------------------------------------------------
// Kernel C: out[b][c][d] = sum_hw coef[b][c][hw] * img[b][d][hw]
// grid (32 d-tiles, 16 b), block (32, 8). Whole coef[b] + img d-tile in SMEM.
// Each thread: d = d0 + tx, classes ty + {0,8,...,72} (10 accumulators).
// -----------------------------------------------------------------------------
__global__ __launch_bounds__(256) void pool_kernel(
    const float* __restrict__ img,   // [B, D, HW]
    float* __restrict__ out)         // [B, C, D]
{
    extern __shared__ float sm[];
    float* coef_s = sm;              // [80][196]
    float* img_s  = sm + C_ * HW_;   // [196][33]  (padded)

    const int tx  = threadIdx.x;     // d lane
    const int ty  = threadIdx.y;     // class group
    const int tid = ty * 32 + tx;
    const int d0  = blockIdx.x * 32;
    const int b   = blockIdx.y;

    const float* coefb = g_scores + (size_t)b * C_ * HW_;
    for (int i = tid; i < C_ * HW_; i += 256) coef_s[i] = coefb[i];

    const float* imgb = img + (size_t)b * D_ * HW_;
    for (int i = tid; i < 32 * HW_; i += 256) {
        int dd = i / HW_, hw = i % HW_;
        img_s[hw * 33 + dd] = imgb[(size_t)(d0 + dd) * HW_ + hw];
    }
    __syncthreads();

    float acc[10];
    #pragma unroll
    for (int k = 0; k < 10; k++) acc[k] = 0.f;

    for (int hw = 0; hw < HW_; hw++) {
        float iv = img_s[hw * 33 + tx];
        #pragma unroll
        for (int k = 0; k < 10; k++)
            acc[k] += coef_s[(ty + 8 * k) * HW_ + hw] * iv;
    }

    #pragma unroll
    for (int k = 0; k < 10; k++)
        out[((size_t)b * C_ + (ty + 8 * k)) * D_ + d0 + tx] = acc[k];
}

// -----------------------------------------------------------------------------

extern "C" void kernel_launch(void* const* d_in, const int* in_sizes, int n_in,
                              void* d_out, int out_size)
{
    // metadata order: batch_size, img_feature_map, word_features, fc_a_w, fc_a_b
    const float* img  = (const float*)d_in[1];
    const float* word = (const float*)d_in[2];
    const float* fw   = (const float*)d_in[3];
    const float* fb   = (const float*)d_in[4];
    float* out = (float*)d_out;

    static int smem_set = 0;
    const int pool_smem = (C_ * HW_ + HW_ * 33) * (int)sizeof(float); // 88592 B
    // Setting a func attribute is idempotent & capture-safe.
    cudaFuncSetAttribute(pool_kernel, cudaFuncAttributeMaxDynamicSharedMemorySize,
                         pool_smem);
    (void)smem_set;

    scores_kernel<<<dim3(7, 5, 16), dim3(32, 4)>>>(img, word, fw, fb);

    softmax_kernel<<<160, 256>>>();

    pool_kernel<<<dim3(32, 16), dim3(32, 8), pool_smem>>>(img, out);
}

// round 2
// speedup vs baseline: 1.8025x; 1.8025x over previous
#include <cuda_runtime.h>
#include <cuda_bf16.h>

#define B_     16
#define C_     80
#define D_     1024
#define HW_    196
#define NSPL   4          // D-split factor
#define DCHUNK (D_ / NSPL)

// partial scores [B*C][NSPL][HW] -> summed+softmaxed into g_coef [B*C][HW]
__device__ float g_part[B_ * C_ * NSPL * HW_];
__device__ float g_coef[B_ * C_ * HW_];

__device__ __forceinline__ float tanh_approx(float x) {
    float y;
    asm("tanh.approx.f32 %0, %1;" : "=f"(y) : "f"(x));
    return y;
}

// -----------------------------------------------------------------------------
// Kernel A: partial[b][c][spl][hw] = sum_{d in spl} tanh(img[b][d][hw]*word[c][d])*fw[d]
// grid (7 hw-tiles, 5 c-tiles, 16*NSPL), block (32,4).
// thread: hw=tx, classes c0+ty+{0,4,8,12}; d chunked by 32 via SMEM.
// -----------------------------------------------------------------------------
__global__ __launch_bounds__(128) void scores_kernel(
    const float* __restrict__ img,   // [B, D, HW]
    const float* __restrict__ word,  // [C, D]
    const float* __restrict__ fw)    // [D]
{
    __shared__ float img_s[32][32];   // [dd][hw]
    __shared__ float word_s[16][32];  // [cc][dd]
    __shared__ float fw_s[32];

    const int tx  = threadIdx.x;
    const int ty  = threadIdx.y;
    const int tid = ty * 32 + tx;
    const int hw0 = blockIdx.x * 32;
    const int c0  = blockIdx.y * 16;
    const int b   = blockIdx.z & (B_ - 1);
    const int spl = blockIdx.z >> 4;
    const int dbase = spl * DCHUNK;

    const float* imgb = img + (size_t)b * D_ * HW_;

    float acc0 = 0.f, acc1 = 0.f, acc2 = 0.f, acc3 = 0.f;

    for (int d0 = dbase; d0 < dbase + DCHUNK; d0 += 32) {
        #pragma unroll
        for (int i = tid; i < 1024; i += 128) {
            int dd = i >> 5, l = i & 31;
            int hw = hw0 + l;
            img_s[dd][l] = (hw < HW_) ? imgb[(size_t)(d0 + dd) * HW_ + hw] : 0.f;
        }
        #pragma unroll
        for (int i = tid; i < 512; i += 128) {
            int cc = i >> 5, dd = i & 31;
            word_s[cc][dd] = word[(size_t)(c0 + cc) * D_ + d0 + dd];
        }
        if (tid < 32) fw_s[tid] = fw[d0 + tid];
        __syncthreads();

        #pragma unroll 8
        for (int dd = 0; dd < 32; dd++) {
            float iv = img_s[dd][tx];
            float w  = fw_s[dd];
            acc0 += tanh_approx(iv * word_s[ty     ][dd]) * w;
            acc1 += tanh_approx(iv * word_s[ty +  4][dd]) * w;
            acc2 += tanh_approx(iv * word_s[ty +  8][dd]) * w;
            acc3 += tanh_approx(iv * word_s[ty + 12][dd]) * w;
        }
        __syncthreads();
    }

    const int hw = hw0 + tx;
    if (hw < HW_) {
        size_t base = (((size_t)b * C_ + c0 + ty) * NSPL + spl) * HW_ + hw;
        g_part[base            ] = acc0;
        g_part[base + 4u*NSPL*HW_ ] = acc1;
        g_part[base + 8u*NSPL*HW_ ] = acc2;
        g_part[base + 12u*NSPL*HW_] = acc3;
    }
}

// -----------------------------------------------------------------------------
// Kernel B: sum the NSPL partials per (b,c) row, softmax over 196 hw -> g_coef.
// (fc_a_b cancels in softmax.) One warp per row; 1280 rows.
// -----------------------------------------------------------------------------
__global__ __launch_bounds__(256) void softmax_kernel()
{
    const int wid  = (blockIdx.x * blockDim.x + threadIdx.x) >> 5;
    const int lane = threadIdx.x & 31;
    if (wid >= B_ * C_) return;

    const float* part = g_part + (size_t)wid * NSPL * HW_;
    float* outrow = g_coef + (size_t)wid * HW_;

    float v[7];
    float m = -1e30f;
    #pragma unroll
    for (int k = 0; k < 7; k++) {
        int i = lane + 32 * k;
        float s = -1e30f;
        if (i < HW_) {
            s = part[i] + part[HW_ + i] + part[2 * HW_ + i] + part[3 * HW_ + i];
        }
        v[k] = s;
        m = fmaxf(m, s);
    }
    #pragma unroll
    for (int o = 16; o; o >>= 1) m = fmaxf(m, __shfl_xor_sync(0xffffffffu, m, o));

    float s = 0.f;
    #pragma unroll
    for (int k = 0; k < 7; k++) { v[k] = __expf(v[k] - m); s += v[k]; }
    #pragma unroll
    for (int o = 16; o; o >>= 1) s += __shfl_xor_sync(0xffffffffu, s, o);

    const float inv = 1.f / s;
    #pragma unroll
    for (int k = 0; k < 7; k++) {
        int i = lane + 32 * k;
        if (i < HW_) outrow[i] = v[k] * inv;
    }
}

// -----------------------------------------------------------------------------
// Kernel C: out[b][c][d] = sum_hw coef[b][c][hw] * img[b][d][hw]
// grid (8 d-tiles of 128, 16 b), block (32,8).
// thread: d = d0 + tx + 32j (j<4), classes ty + 8k (k<10)  -> 40 accumulators.
// coef[b] (80x196) + transposed img tile (196x129 padded) in SMEM.
// -----------------------------------------------------------------------------
#define DT_ 128
__global__ __launch_bounds__(256) void pool_kernel(
    const float* __restrict__ img,   // [B, D, HW]
    float* __restrict__ out)         // [B, C, D]
{
    extern __shared__ float sm[];
    float* coef_s = sm;                 // [80][196]
    float* img_s  = sm + C_ * HW_;      // [196][129]  (padded)

    const int tx  = threadIdx.x;
    const int ty  = threadIdx.y;
    const int tid = ty * 32 + tx;
    const int d0  = blockIdx.x * DT_;
    const int b   = blockIdx.y;

    const float* coefb = g_coef + (size_t)b * C_ * HW_;
    for (int i = tid; i < C_ * HW_; i += 256) coef_s[i] = coefb[i];

    const float* imgb = img + (size_t)b * D_ * HW_;
    for (int i = tid; i < DT_ * HW_; i += 256) {
        int dd = i / HW_, hw = i - dd * HW_;
        img_s[hw * (DT_ + 1) + dd] = imgb[(size_t)(d0 + dd) * HW_ + hw];
    }
    __syncthreads();

    float acc[4][10];
    #pragma unroll
    for (int j = 0; j < 4; j++)
        #pragma unroll
        for (int k = 0; k < 10; k++) acc[j][k] = 0.f;

    for (int hw = 0; hw < HW_; hw++) {
        float iv[4];
        #pragma unroll
        for (int j = 0; j < 4; j++) iv[j] = img_s[hw * (DT_ + 1) + tx + 32 * j];
        #pragma unroll
        for (int k = 0; k < 10; k++) {
            float cv = coef_s[(ty + 8 * k) * HW_ + hw];
            #pragma unroll
            for (int j = 0; j < 4; j++) acc[j][k] += cv * iv[j];
        }
    }

    #pragma unroll
    for (int k = 0; k < 10; k++)
        #pragma unroll
        for (int j = 0; j < 4; j++)
            out[((size_t)b * C_ + (ty + 8 * k)) * D_ + d0 + tx + 32 * j] = acc[j][k];
}

// -----------------------------------------------------------------------------

extern "C" void kernel_launch(void* const* d_in, const int* in_sizes, int n_in,
                              void* d_out, int out_size)
{
    // metadata order: batch_size, img_feature_map, word_features, fc_a_w, fc_a_b
    const float* img  = (const float*)d_in[1];
    const float* word = (const float*)d_in[2];
    const float* fw   = (const float*)d_in[3];
    float* out = (float*)d_out;

    const int pool_smem = (C_ * HW_ + HW_ * (DT_ + 1)) * (int)sizeof(float); // 163856 B
    cudaFuncSetAttribute(pool_kernel, cudaFuncAttributeMaxDynamicSharedMemorySize,
                         pool_smem);

    scores_kernel<<<dim3(7, 5, B_ * NSPL), dim3(32, 4)>>>(img, word, fw);

    softmax_kernel<<<160, 256>>>();

    pool_kernel<<<dim3(D_ / DT_, B_), dim3(32, 8), pool_smem>>>(img, out);
}

// round 3
// speedup vs baseline: 1.9232x; 1.0670x over previous
#include <cuda_runtime.h>
#include <cuda_bf16.h>

#define B_     16
#define C_     80
#define D_     1024
#define HW_    196
#define NSPL   8          // D-split factor
#define DCHUNK (D_ / NSPL)   // 128

// partial scores [B*C][NSPL][HW] -> summed+softmaxed into g_coef [B*C][HW]
__device__ float g_part[B_ * C_ * NSPL * HW_];
__device__ float g_coef[B_ * C_ * HW_];

// pack two f32 -> f16x2  (lo half = a, hi half = b)
__device__ __forceinline__ unsigned pack_h2(float a, float b) {
    unsigned r;
    asm("cvt.rn.f16x2.f32 %0, %2, %1;" : "=r"(r) : "f"(a), "f"(b));
    return r;
}

// acc (f32x2) += tanh(iv2*w2) (f16x2, widened) * fw2 (f32x2)
__device__ __forceinline__ void acc_step(unsigned long long& acc, unsigned iv2,
                                         unsigned w2, unsigned long long fw2) {
    unsigned x2, t2;
    asm("mul.rn.f16x2 %0, %1, %2;" : "=r"(x2) : "r"(iv2), "r"(w2));
    asm("tanh.approx.f16x2 %0, %1;" : "=r"(t2) : "r"(x2));
    unsigned long long tf;
    asm("{\n\t"
        ".reg .b16 l, h;\n\t"
        ".reg .f32 fl, fh;\n\t"
        "mov.b32 {l, h}, %1;\n\t"
        "cvt.f32.f16 fl, l;\n\t"
        "cvt.f32.f16 fh, h;\n\t"
        "mov.b64 %0, {fl, fh};\n\t"
        "}" : "=l"(tf) : "r"(t2));
    asm("fma.rn.f32x2 %0, %1, %2, %0;" : "+l"(acc) : "l"(tf), "l"(fw2));
}

// -----------------------------------------------------------------------------
// Kernel A: partial[b][c][spl][hw] = sum_{d in spl} tanh(img*word)*fw
// grid (7 hw-tiles, 5 c-tiles, B*NSPL), block (32,4).
// d processed as f16x2 pairs; accumulate f32x2.
// -----------------------------------------------------------------------------
__global__ __launch_bounds__(128) void scores_kernel(
    const float* __restrict__ img,   // [B, D, HW]
    const float* __restrict__ word,  // [C, D]
    const float* __restrict__ fw)    // [D]
{
    __shared__ unsigned img2_s[16][32];            // f16x2 [ddp][hw]
    __shared__ unsigned word2_s[16][16];           // f16x2 [cc][ddp]
    __shared__ unsigned long long fw2_s[16];       // f32x2 [ddp]

    const int tx  = threadIdx.x;
    const int ty  = threadIdx.y;
    const int tid = ty * 32 + tx;
    const int hw0 = blockIdx.x * 32;
    const int c0  = blockIdx.y * 16;
    const int b   = blockIdx.z & (B_ - 1);
    const int spl = blockIdx.z >> 4;
    const int dbase = spl * DCHUNK;

    const float* imgb = img + (size_t)b * D_ * HW_;

    unsigned long long acc[4] = {0ull, 0ull, 0ull, 0ull};

    for (int d0 = dbase; d0 < dbase + DCHUNK; d0 += 32) {
        // img pairs: [16 ddp][32 hw]
        #pragma unroll
        for (int i = tid; i < 512; i += 128) {
            int ddp = i >> 5, l = i & 31;
            int hw = hw0 + l;
            float a = 0.f, bb = 0.f;
            if (hw < HW_) {
                a  = imgb[(size_t)(d0 + 2 * ddp)     * HW_ + hw];
                bb = imgb[(size_t)(d0 + 2 * ddp + 1) * HW_ + hw];
            }
            img2_s[ddp][l] = pack_h2(a, bb);
        }
        // word pairs: [16 cc][16 ddp]  (d-contiguous -> float2 loads)
        #pragma unroll
        for (int i = tid; i < 256; i += 128) {
            int cc = i >> 4, ddp = i & 15;
            float2 w = *(const float2*)&word[(size_t)(c0 + cc) * D_ + d0 + 2 * ddp];
            word2_s[cc][ddp] = pack_h2(w.x, w.y);
        }
        if (tid < 16) fw2_s[tid] = *(const unsigned long long*)&fw[d0 + 2 * tid];
        __syncthreads();

        #pragma unroll 4
        for (int ddp = 0; ddp < 16; ddp++) {
            unsigned iv2 = img2_s[ddp][tx];
            unsigned long long fw2 = fw2_s[ddp];
            acc_step(acc[0], iv2, word2_s[ty     ][ddp], fw2);
            acc_step(acc[1], iv2, word2_s[ty +  4][ddp], fw2);
            acc_step(acc[2], iv2, word2_s[ty +  8][ddp], fw2);
            acc_step(acc[3], iv2, word2_s[ty + 12][ddp], fw2);
        }
        __syncthreads();
    }

    const int hw = hw0 + tx;
    if (hw < HW_) {
        #pragma unroll
        for (int k = 0; k < 4; k++) {
            float lo, hi;
            asm("mov.b64 {%0, %1}, %2;" : "=f"(lo), "=f"(hi) : "l"(acc[k]));
            int c = c0 + ty + 4 * k;
            g_part[(((size_t)b * C_ + c) * NSPL + spl) * HW_ + hw] = lo + hi;
        }
    }
}

// -----------------------------------------------------------------------------
// Kernel B: sum NSPL partials per (b,c) row, softmax over 196 hw -> g_coef.
// (fc_a_b cancels in softmax.) One warp per row; 1280 rows.
// -----------------------------------------------------------------------------
__global__ __launch_bounds__(256) void softmax_kernel()
{
    const int wid  = (blockIdx.x * blockDim.x + threadIdx.x) >> 5;
    const int lane = threadIdx.x & 31;
    if (wid >= B_ * C_) return;

    const float* part = g_part + (size_t)wid * NSPL * HW_;
    float* outrow = g_coef + (size_t)wid * HW_;

    float v[7];
    float m = -1e30f;
    #pragma unroll
    for (int k = 0; k < 7; k++) {
        int i = lane + 32 * k;
        float s = -1e30f;
        if (i < HW_) {
            s = 0.f;
            #pragma unroll
            for (int p = 0; p < NSPL; p++) s += part[p * HW_ + i];
        }
        v[k] = s;
        m = fmaxf(m, s);
    }
    #pragma unroll
    for (int o = 16; o; o >>= 1) m = fmaxf(m, __shfl_xor_sync(0xffffffffu, m, o));

    float s = 0.f;
    #pragma unroll
    for (int k = 0; k < 7; k++) { v[k] = __expf(v[k] - m); s += v[k]; }
    #pragma unroll
    for (int o = 16; o; o >>= 1) s += __shfl_xor_sync(0xffffffffu, s, o);

    const float inv = 1.f / s;
    #pragma unroll
    for (int k = 0; k < 7; k++) {
        int i = lane + 32 * k;
        if (i < HW_) outrow[i] = v[k] * inv;
    }
}

// -----------------------------------------------------------------------------
// Kernel C: out[b][c][d] = sum_hw coef[b][c][hw] * img[b][d][hw]
// grid (8 d-tiles of 128, 16 b), block (32,8).
// thread: d = d0 + tx + 32j (j<4), classes ty + 8k (k<10)  -> 40 accumulators.
// -----------------------------------------------------------------------------
#define DT_ 128
__global__ __launch_bounds__(256) void pool_kernel(
    const float* __restrict__ img,   // [B, D, HW]
    float* __restrict__ out)         // [B, C, D]
{
    extern __shared__ float sm[];
    float* coef_s = sm;                 // [80][196]
    float* img_s  = sm + C_ * HW_;      // [196][129]  (padded)

    const int tx  = threadIdx.x;
    const int ty  = threadIdx.y;
    const int tid = ty * 32 + tx;
    const int d0  = blockIdx.x * DT_;
    const int b   = blockIdx.y;

    const float* coefb = g_coef + (size_t)b * C_ * HW_;
    for (int i = tid; i < C_ * HW_; i += 256) coef_s[i] = coefb[i];

    const float* imgb = img + (size_t)b * D_ * HW_;
    for (int i = tid; i < DT_ * HW_; i += 256) {
        int dd = i / HW_, hw = i - dd * HW_;
        img_s[hw * (DT_ + 1) + dd] = imgb[(size_t)(d0 + dd) * HW_ + hw];
    }
    __syncthreads();

    float acc[4][10];
    #pragma unroll
    for (int j = 0; j < 4; j++)
        #pragma unroll
        for (int k = 0; k < 10; k++) acc[j][k] = 0.f;

    for (int hw = 0; hw < HW_; hw++) {
        float iv[4];
        #pragma unroll
        for (int j = 0; j < 4; j++) iv[j] = img_s[hw * (DT_ + 1) + tx + 32 * j];
        #pragma unroll
        for (int k = 0; k < 10; k++) {
            float cv = coef_s[(ty + 8 * k) * HW_ + hw];
            #pragma unroll
            for (int j = 0; j < 4; j++) acc[j][k] += cv * iv[j];
        }
    }

    #pragma unroll
    for (int k = 0; k < 10; k++)
        #pragma unroll
        for (int j = 0; j < 4; j++)
            out[((size_t)b * C_ + (ty + 8 * k)) * D_ + d0 + tx + 32 * j] = acc[j][k];
}

// -----------------------------------------------------------------------------

extern "C" void kernel_launch(void* const* d_in, const int* in_sizes, int n_in,
                              void* d_out, int out_size)
{
    // metadata order: batch_size, img_feature_map, word_features, fc_a_w, fc_a_b
    const float* img  = (const float*)d_in[1];
    const float* word = (const float*)d_in[2];
    const float* fw   = (const float*)d_in[3];
    float* out = (float*)d_out;

    const int pool_smem = (C_ * HW_ + HW_ * (DT_ + 1)) * (int)sizeof(float); // 163856 B
    cudaFuncSetAttribute(pool_kernel, cudaFuncAttributeMaxDynamicSharedMemorySize,
                         pool_smem);

    scores_kernel<<<dim3(7, 5, B_ * NSPL), dim3(32, 4)>>>(img, word, fw);

    softmax_kernel<<<160, 256>>>();

    pool_kernel<<<dim3(D_ / DT_, B_), dim3(32, 8), pool_smem>>>(img, out);
}

// round 4
// speedup vs baseline: 2.3145x; 1.2035x over previous
#include <cuda_runtime.h>
#include <cuda_bf16.h>

#define B_     16
#define C_     80
#define D_     1024
#define HW_    196
#define NSPL   8
#define DCHUNK (D_ / NSPL)   // 128

__device__ float g_part[B_ * C_ * NSPL * HW_];
__device__ float g_coef[B_ * C_ * HW_];

__device__ __forceinline__ unsigned pack_h2(float a, float b) {
    unsigned r;
    asm("cvt.rn.f16x2.f32 %0, %2, %1;" : "=r"(r) : "f"(a), "f"(b));
    return r;
}

// acc (f32x2) += widen(tanh(iv2*w2)) * fw2
__device__ __forceinline__ void acc_step(unsigned long long& acc, unsigned iv2,
                                         unsigned w2, unsigned long long fw2) {
    unsigned x2, t2;
    asm("mul.rn.f16x2 %0, %1, %2;" : "=r"(x2) : "r"(iv2), "r"(w2));
    asm("tanh.approx.f16x2 %0, %1;" : "=r"(t2) : "r"(x2));
    unsigned long long tf;
    asm("{\n\t"
        ".reg .b16 l, h;\n\t"
        ".reg .f32 fl, fh;\n\t"
        "mov.b32 {l, h}, %1;\n\t"
        "cvt.f32.f16 fl, l;\n\t"
        "cvt.f32.f16 fh, h;\n\t"
        "mov.b64 %0, {fl, fh};\n\t"
        "}" : "=l"(tf) : "r"(t2));
    asm("fma.rn.f32x2 %0, %1, %2, %0;" : "+l"(acc) : "l"(tf), "l"(fw2));
}

// -----------------------------------------------------------------------------
// Kernel A: partial scores. grid (7 hw, 5 c, B*NSPL), block (32,4).
// word tile stored as [ddp][ty*4+k] so each thread's 4 class weights are one
// broadcast LDS.128.
// -----------------------------------------------------------------------------
__global__ __launch_bounds__(128, 10) void scores_kernel(
    const float* __restrict__ img,   // [B, D, HW]
    const float* __restrict__ word,  // [C, D]
    const float* __restrict__ fw)    // [D]
{
    __shared__ unsigned img2_s[16][32];                 // f16x2 [ddp][hw]
    __shared__ __align__(16) unsigned word2_s[16][16];  // f16x2 [ddp][ty*4+k]
    __shared__ unsigned long long fw2_s[16];            // f32x2 [ddp]

    const int tx  = threadIdx.x;
    const int ty  = threadIdx.y;
    const int tid = ty * 32 + tx;
    const int hw0 = blockIdx.x * 32;
    const int c0  = blockIdx.y * 16;
    const int b   = blockIdx.z & (B_ - 1);
    const int spl = blockIdx.z >> 4;
    const int dbase = spl * DCHUNK;

    const float* imgb = img + (size_t)b * D_ * HW_;

    unsigned long long acc[4] = {0ull, 0ull, 0ull, 0ull};

    for (int d0 = dbase; d0 < dbase + DCHUNK; d0 += 32) {
        #pragma unroll
        for (int i = tid; i < 512; i += 128) {
            int ddp = i >> 5, l = i & 31;
            int hw = hw0 + l;
            float a = 0.f, bb = 0.f;
            if (hw < HW_) {
                a  = imgb[(size_t)(d0 + 2 * ddp)     * HW_ + hw];
                bb = imgb[(size_t)(d0 + 2 * ddp + 1) * HW_ + hw];
            }
            img2_s[ddp][l] = pack_h2(a, bb);
        }
        // class cc = (pos&3) + 4*(pos>>2)  <=>  pos = (cc&3)*4 + (cc>>2)
        #pragma unroll
        for (int i = tid; i < 256; i += 128) {
            int cc = i >> 4, ddp = i & 15;
            float2 w = *(const float2*)&word[(size_t)(c0 + cc) * D_ + d0 + 2 * ddp];
            word2_s[ddp][(cc & 3) * 4 + (cc >> 2)] = pack_h2(w.x, w.y);
        }
        if (tid < 16) fw2_s[tid] = *(const unsigned long long*)&fw[d0 + 2 * tid];
        __syncthreads();

        #pragma unroll 8
        for (int ddp = 0; ddp < 16; ddp++) {
            unsigned iv2 = img2_s[ddp][tx];
            unsigned long long fw2 = fw2_s[ddp];
            uint4 w4 = *(const uint4*)&word2_s[ddp][ty * 4];
            acc_step(acc[0], iv2, w4.x, fw2);
            acc_step(acc[1], iv2, w4.y, fw2);
            acc_step(acc[2], iv2, w4.z, fw2);
            acc_step(acc[3], iv2, w4.w, fw2);
        }
        __syncthreads();
    }

    const int hw = hw0 + tx;
    if (hw < HW_) {
        #pragma unroll
        for (int k = 0; k < 4; k++) {
            float lo, hi;
            asm("mov.b64 {%0, %1}, %2;" : "=f"(lo), "=f"(hi) : "l"(acc[k]));
            int c = c0 + ty + 4 * k;
            g_part[(((size_t)b * C_ + c) * NSPL + spl) * HW_ + hw] = lo + hi;
        }
    }
}

// -----------------------------------------------------------------------------
// Kernel B: sum NSPL partials, softmax over 196 hw -> g_coef. One warp/row.
// -----------------------------------------------------------------------------
__global__ __launch_bounds__(256) void softmax_kernel()
{
    const int wid  = (blockIdx.x * blockDim.x + threadIdx.x) >> 5;
    const int lane = threadIdx.x & 31;
    if (wid >= B_ * C_) return;

    const float* part = g_part + (size_t)wid * NSPL * HW_;
    float* outrow = g_coef + (size_t)wid * HW_;

    float v[7];
    float m = -1e30f;
    #pragma unroll
    for (int k = 0; k < 7; k++) {
        int i = lane + 32 * k;
        float s = -1e30f;
        if (i < HW_) {
            s = 0.f;
            #pragma unroll
            for (int p = 0; p < NSPL; p++) s += part[p * HW_ + i];
        }
        v[k] = s;
        m = fmaxf(m, s);
    }
    #pragma unroll
    for (int o = 16; o; o >>= 1) m = fmaxf(m, __shfl_xor_sync(0xffffffffu, m, o));

    float s = 0.f;
    #pragma unroll
    for (int k = 0; k < 7; k++) { v[k] = __expf(v[k] - m); s += v[k]; }
    #pragma unroll
    for (int o = 16; o; o >>= 1) s += __shfl_xor_sync(0xffffffffu, s, o);

    const float inv = 1.f / s;
    #pragma unroll
    for (int k = 0; k < 7; k++) {
        int i = lane + 32 * k;
        if (i < HW_) outrow[i] = v[k] * inv;
    }
}

// -----------------------------------------------------------------------------
// Kernel C: out[b][c][d] = sum_hw coef[b][c][hw] * img[b][d][hw]
// grid (8 d-tiles of 128, 16 b), block (32,8). f32x2 math on adjacent-d pairs:
// thread d-pairs at d0 + 2*tx + 64*j (j<2), classes ty + 8k (k<10).
// -----------------------------------------------------------------------------
#define DT_   128
#define IPAD_ 130   // even pad -> 8B-aligned float2 LDS
__global__ __launch_bounds__(256) void pool_kernel(
    const float* __restrict__ img,   // [B, D, HW]
    float* __restrict__ out)         // [B, C, D]
{
    extern __shared__ float sm[];
    float* coef_s = sm;                 // [80][196]
    float* img_s  = sm + C_ * HW_;      // [196][IPAD_]

    const int tx  = threadIdx.x;
    const int ty  = threadIdx.y;
    const int tid = ty * 32 + tx;
    const int d0  = blockIdx.x * DT_;
    const int b   = blockIdx.y;

    const float* coefb = g_coef + (size_t)b * C_ * HW_;
    for (int i = tid; i < C_ * HW_; i += 256) coef_s[i] = coefb[i];

    const float* imgb = img + (size_t)b * D_ * HW_;
    for (int i = tid; i < DT_ * HW_; i += 256) {
        int dd = i / HW_, hw = i - dd * HW_;
        img_s[hw * IPAD_ + dd] = imgb[(size_t)(d0 + dd) * HW_ + hw];
    }
    __syncthreads();

    unsigned long long acc[2][10];
    #pragma unroll
    for (int j = 0; j < 2; j++)
        #pragma unroll
        for (int k = 0; k < 10; k++) acc[j][k] = 0ull;

    for (int hw = 0; hw < HW_; hw++) {
        unsigned long long iv[2];
        #pragma unroll
        for (int j = 0; j < 2; j++)
            iv[j] = *(const unsigned long long*)&img_s[hw * IPAD_ + 2 * tx + 64 * j];
        #pragma unroll
        for (int k = 0; k < 10; k++) {
            float cv = coef_s[(ty + 8 * k) * HW_ + hw];
            unsigned long long cv2;
            asm("mov.b64 %0, {%1, %1};" : "=l"(cv2) : "f"(cv));
            #pragma unroll
            for (int j = 0; j < 2; j++)
                asm("fma.rn.f32x2 %0, %1, %2, %0;" : "+l"(acc[j][k]) : "l"(cv2), "l"(iv[j]));
        }
    }

    #pragma unroll
    for (int k = 0; k < 10; k++)
        #pragma unroll
        for (int j = 0; j < 2; j++) {
            float lo, hi;
            asm("mov.b64 {%0, %1}, %2;" : "=f"(lo), "=f"(hi) : "l"(acc[j][k]));
            size_t o = ((size_t)b * C_ + (ty + 8 * k)) * D_ + d0 + 2 * tx + 64 * j;
            *(float2*)&out[o] = make_float2(lo, hi);
        }
}

// -----------------------------------------------------------------------------

extern "C" void kernel_launch(void* const* d_in, const int* in_sizes, int n_in,
                              void* d_out, int out_size)
{
    const float* img  = (const float*)d_in[1];
    const float* word = (const float*)d_in[2];
    const float* fw   = (const float*)d_in[3];
    float* out = (float*)d_out;

    const int pool_smem = (C_ * HW_ + HW_ * IPAD_) * (int)sizeof(float); // 164640 B
    cudaFuncSetAttribute(pool_kernel, cudaFuncAttributeMaxDynamicSharedMemorySize,
                         pool_smem);

    scores_kernel<<<dim3(7, 5, B_ * NSPL), dim3(32, 4)>>>(img, word, fw);

    softmax_kernel<<<160, 256>>>();

    pool_kernel<<<dim3(D_ / DT_, B_), dim3(32, 8), pool_smem>>>(img, out);
}

// round 5
// speedup vs baseline: 2.3962x; 1.0353x over previous
#include <cuda_runtime.h>
#include <cuda_bf16.h>

#define B_     16
#define C_     80
#define D_     1024
#define HW_    196
#define NSPL   8
#define DCHUNK (D_ / NSPL)   // 128

__device__ float g_part[B_ * C_ * NSPL * HW_];
__device__ float g_coef[B_ * C_ * HW_];

__device__ __forceinline__ unsigned pack_h2(float a, float b) {
    unsigned r;
    asm("cvt.rn.f16x2.f32 %0, %2, %1;" : "=r"(r) : "f"(a), "f"(b));
    return r;
}

__device__ __forceinline__ unsigned tanh_h2(unsigned x) {
    unsigned y;
    asm("tanh.approx.f16x2 %0, %1;" : "=r"(y) : "r"(x));
    return y;
}
__device__ __forceinline__ unsigned mul_h2(unsigned a, unsigned b) {
    unsigned y;
    asm("mul.rn.f16x2 %0, %1, %2;" : "=r"(y) : "r"(a), "r"(b));
    return y;
}

// -----------------------------------------------------------------------------
// Kernel A: partial[b][c][spl][hw] = sum_{d in spl} tanh(img*word)*fw
// HMMA formulation: per warp, A = tanh values [16 hw x 16 d] (f16), B = fw in
// n-column 0 (f16), D accumulated in exact f32 fragments. No F2F widens.
// grid (13 hw16-tiles, 5 c16-tiles, B*NSPL), block 128 (4 warps, 4 classes each).
// -----------------------------------------------------------------------------
__global__ __launch_bounds__(128) void scores_kernel(
    const float* __restrict__ img,   // [B, D, HW]
    const float* __restrict__ word,  // [C, D]
    const float* __restrict__ fw)    // [D]
{
    __shared__ unsigned img2_s[16][24];   // f16x2 [dpair][hw]  (pad 24: conflict-free lane pattern)
    __shared__ unsigned word2_s[16][16];  // f16x2 [cc][dpair]
    __shared__ unsigned fwh2_s[16];       // f16x2 [dpair]

    const int tid  = threadIdx.x;
    const int warp = tid >> 5;
    const int lane = tid & 31;
    const int q    = lane & 3;    // k-pair group
    const int g    = lane >> 2;   // row group
    const int hw0  = blockIdx.x * 16;
    const int c0   = blockIdx.y * 16;
    const int b    = blockIdx.z & (B_ - 1);
    const int spl  = blockIdx.z >> 4;
    const int dbase = spl * DCHUNK;

    const float* imgb = img + (size_t)b * D_ * HW_;

    // 4 classes per warp, each with an m16n8 f32 accumulator fragment
    float dacc[4][4];
    #pragma unroll
    for (int j = 0; j < 4; j++)
        #pragma unroll
        for (int r = 0; r < 4; r++) dacc[j][r] = 0.f;

    for (int d0 = dbase; d0 < dbase + DCHUNK; d0 += 32) {
        // img pairs: [16 dpair][16 hw]
        #pragma unroll
        for (int i = tid; i < 256; i += 128) {
            int dp = i >> 4, hl = i & 15;
            int hw = hw0 + hl;
            float a = 0.f, bb = 0.f;
            if (hw < HW_) {
                a  = imgb[(size_t)(d0 + 2 * dp)     * HW_ + hw];
                bb = imgb[(size_t)(d0 + 2 * dp + 1) * HW_ + hw];
            }
            img2_s[dp][hl] = pack_h2(a, bb);
        }
        // word pairs: [16 cc][16 dpair]
        #pragma unroll
        for (int i = tid; i < 256; i += 128) {
            int cc = i >> 4, dp = i & 15;
            float2 w = *(const float2*)&word[(size_t)(c0 + cc) * D_ + d0 + 2 * dp];
            word2_s[cc][dp] = pack_h2(w.x, w.y);
        }
        if (tid < 16)
            fwh2_s[tid] = pack_h2(fw[d0 + 2 * tid], fw[d0 + 2 * tid + 1]);
        __syncthreads();

        #pragma unroll
        for (int kc = 0; kc < 2; kc++) {
            const int p0 = kc * 8 + q;       // pair index for a0/a1, b0
            const int p1 = p0 + 4;           // pair index for a2/a3, b1
            const unsigned iv00 = img2_s[p0][g];
            const unsigned iv01 = img2_s[p0][g + 8];
            const unsigned iv10 = img2_s[p1][g];
            const unsigned iv11 = img2_s[p1][g + 8];
            const unsigned fb0 = (lane < 4) ? fwh2_s[p0] : 0u;  // B col 0 only
            const unsigned fb1 = (lane < 4) ? fwh2_s[p1] : 0u;

            #pragma unroll
            for (int j = 0; j < 4; j++) {
                const int cl = warp * 4 + j;
                const unsigned wA = word2_s[cl][p0];
                const unsigned wB = word2_s[cl][p1];
                unsigned a0 = tanh_h2(mul_h2(iv00, wA));
                unsigned a1 = tanh_h2(mul_h2(iv01, wA));
                unsigned a2 = tanh_h2(mul_h2(iv10, wB));
                unsigned a3 = tanh_h2(mul_h2(iv11, wB));
                asm("mma.sync.aligned.m16n8k16.row.col.f32.f16.f16.f32 "
                    "{%0,%1,%2,%3}, {%4,%5,%6,%7}, {%8,%9}, {%0,%1,%2,%3};"
                    : "+f"(dacc[j][0]), "+f"(dacc[j][1]),
                      "+f"(dacc[j][2]), "+f"(dacc[j][3])
                    : "r"(a0), "r"(a1), "r"(a2), "r"(a3), "r"(fb0), "r"(fb1));
            }
        }
        __syncthreads();
    }

    // Epilogue: column 0 of D = scores. Lanes with q==0 hold rows g (c0) and g+8 (c2).
    if (q == 0) {
        #pragma unroll
        for (int j = 0; j < 4; j++) {
            const int c = c0 + warp * 4 + j;
            const size_t rowbase = (((size_t)b * C_ + c) * NSPL + spl) * HW_;
            const int hw1 = hw0 + g;
            const int hw2 = hw0 + g + 8;
            if (hw1 < HW_) g_part[rowbase + hw1] = dacc[j][0];
            if (hw2 < HW_) g_part[rowbase + hw2] = dacc[j][2];
        }
    }
}

// -----------------------------------------------------------------------------
// Kernel B: sum NSPL partials, softmax over 196 hw -> g_coef. One warp/row.
// -----------------------------------------------------------------------------
__global__ __launch_bounds__(256) void softmax_kernel()
{
    const int wid  = (blockIdx.x * blockDim.x + threadIdx.x) >> 5;
    const int lane = threadIdx.x & 31;
    if (wid >= B_ * C_) return;

    const float* part = g_part + (size_t)wid * NSPL * HW_;
    float* outrow = g_coef + (size_t)wid * HW_;

    float v[7];
    float m = -1e30f;
    #pragma unroll
    for (int k = 0; k < 7; k++) {
        int i = lane + 32 * k;
        float s = -1e30f;
        if (i < HW_) {
            s = 0.f;
            #pragma unroll
            for (int p = 0; p < NSPL; p++) s += part[p * HW_ + i];
        }
        v[k] = s;
        m = fmaxf(m, s);
    }
    #pragma unroll
    for (int o = 16; o; o >>= 1) m = fmaxf(m, __shfl_xor_sync(0xffffffffu, m, o));

    float s = 0.f;
    #pragma unroll
    for (int k = 0; k < 7; k++) { v[k] = __expf(v[k] - m); s += v[k]; }
    #pragma unroll
    for (int o = 16; o; o >>= 1) s += __shfl_xor_sync(0xffffffffu, s, o);

    const float inv = 1.f / s;
    #pragma unroll
    for (int k = 0; k < 7; k++) {
        int i = lane + 32 * k;
        if (i < HW_) outrow[i] = v[k] * inv;
    }
}

// -----------------------------------------------------------------------------
// Kernel C: out[b][c][d] = sum_hw coef[b][c][hw] * img[b][d][hw]
// grid (8 d-tiles of 128, 16 b), block (32,8). f32x2 math on adjacent-d pairs.
// -----------------------------------------------------------------------------
#define DT_   128
#define IPAD_ 130
__global__ __launch_bounds__(256) void pool_kernel(
    const float* __restrict__ img,   // [B, D, HW]
    float* __restrict__ out)         // [B, C, D]
{
    extern __shared__ float sm[];
    float* coef_s = sm;                 // [80][196]
    float* img_s  = sm + C_ * HW_;      // [196][IPAD_]

    const int tx  = threadIdx.x;
    const int ty  = threadIdx.y;
    const int tid = ty * 32 + tx;
    const int d0  = blockIdx.x * DT_;
    const int b   = blockIdx.y;

    const float* coefb = g_coef + (size_t)b * C_ * HW_;
    for (int i = tid; i < C_ * HW_; i += 256) coef_s[i] = coefb[i];

    const float* imgb = img + (size_t)b * D_ * HW_;
    for (int i = tid; i < DT_ * HW_; i += 256) {
        int dd = i / HW_, hw = i - dd * HW_;
        img_s[hw * IPAD_ + dd] = imgb[(size_t)(d0 + dd) * HW_ + hw];
    }
    __syncthreads();

    unsigned long long acc[2][10];
    #pragma unroll
    for (int j = 0; j < 2; j++)
        #pragma unroll
        for (int k = 0; k < 10; k++) acc[j][k] = 0ull;

    for (int hw = 0; hw < HW_; hw++) {
        unsigned long long iv[2];
        #pragma unroll
        for (int j = 0; j < 2; j++)
            iv[j] = *(const unsigned long long*)&img_s[hw * IPAD_ + 2 * tx + 64 * j];
        #pragma unroll
        for (int k = 0; k < 10; k++) {
            float cv = coef_s[(ty + 8 * k) * HW_ + hw];
            unsigned long long cv2;
            asm("mov.b64 %0, {%1, %1};" : "=l"(cv2) : "f"(cv));
            #pragma unroll
            for (int j = 0; j < 2; j++)
                asm("fma.rn.f32x2 %0, %1, %2, %0;" : "+l"(acc[j][k]) : "l"(cv2), "l"(iv[j]));
        }
    }

    #pragma unroll
    for (int k = 0; k < 10; k++)
        #pragma unroll
        for (int j = 0; j < 2; j++) {
            float lo, hi;
            asm("mov.b64 {%0, %1}, %2;" : "=f"(lo), "=f"(hi) : "l"(acc[j][k]));
            size_t o = ((size_t)b * C_ + (ty + 8 * k)) * D_ + d0 + 2 * tx + 64 * j;
            *(float2*)&out[o] = make_float2(lo, hi);
        }
}

// -----------------------------------------------------------------------------

extern "C" void kernel_launch(void* const* d_in, const int* in_sizes, int n_in,
                              void* d_out, int out_size)
{
    const float* img  = (const float*)d_in[1];
    const float* word = (const float*)d_in[2];
    const float* fw   = (const float*)d_in[3];
    float* out = (float*)d_out;

    const int pool_smem = (C_ * HW_ + HW_ * IPAD_) * (int)sizeof(float); // 164640 B
    cudaFuncSetAttribute(pool_kernel, cudaFuncAttributeMaxDynamicSharedMemorySize,
                         pool_smem);

    scores_kernel<<<dim3(13, 5, B_ * NSPL), 128>>>(img, word, fw);

    softmax_kernel<<<160, 256>>>();

    pool_kernel<<<dim3(D_ / DT_, B_), dim3(32, 8), pool_smem>>>(img, out);
}